// round 4
// baseline (speedup 1.0000x reference)
#include <cuda_runtime.h>

#define N_NODES 100000
#define N_EDGES 1600000
#define SCAN_BLOCKS 98   // ceil(100000/1024)

// ---------------- scratch (device globals; no allocation allowed) ----------------
__device__ int   g_deg[N_NODES];
__device__ int   g_rowptr[N_NODES];
__device__ int   g_cursor[N_NODES];
__device__ int   g_bsum[128];
__device__ int   g_bscan[128];
__device__ int   g_csrc[N_EDGES];
__device__ float g_cw[N_EDGES];
__device__ float g_sup[(size_t)N_NODES * 64];
__device__ float g_h[(size_t)N_NODES * 64];
__device__ float g_sup3[(size_t)N_NODES * 16];

// ---------------- CSR build ----------------
__global__ void k_zero_deg() {
    int i = blockIdx.x * blockDim.x + threadIdx.x;
    if (i < N_NODES) g_deg[i] = 0;
}

__global__ void k_hist(const int* __restrict__ dst) {
    int i = blockIdx.x * blockDim.x + threadIdx.x;
    if (i < N_EDGES) atomicAdd(&g_deg[dst[i]], 1);
}

// pass 1: per-1024-chunk sums
__global__ void k_scan1() {
    int b = blockIdx.x, t = threadIdx.x;
    int base = b * 1024 + t * 4;
    int s = 0;
#pragma unroll
    for (int j = 0; j < 4; j++) {
        int idx = base + j;
        if (idx < N_NODES) s += g_deg[idx];
    }
#pragma unroll
    for (int off = 16; off; off >>= 1) s += __shfl_down_sync(0xffffffffu, s, off);
    __shared__ int ws[8];
    if ((t & 31) == 0) ws[t >> 5] = s;
    __syncthreads();
    if (t == 0) {
        int tot = 0;
        for (int i = 0; i < 8; i++) tot += ws[i];
        g_bsum[b] = tot;
    }
}

// pass 2: exclusive scan of chunk sums (single block, 128 threads)
__global__ void k_scan2(int nblocks) {
    int t = threadIdx.x;
    int v = (t < nblocks) ? g_bsum[t] : 0;
    __shared__ int arr[128];
    arr[t] = v;
    __syncthreads();
    for (int off = 1; off < 128; off <<= 1) {
        int x = (t >= off) ? arr[t - off] : 0;
        __syncthreads();
        arr[t] += x;
        __syncthreads();
    }
    if (t < nblocks) g_bscan[t] = arr[t] - v;
}

// pass 3: per-chunk exclusive scan + chunk offset -> rowptr, cursor
__global__ void k_scan3() {
    int b = blockIdx.x, t = threadIdx.x;
    int base = b * 1024 + t * 4;
    int v0, v1, v2, v3;
    {
        int i0 = base, i1 = base + 1, i2 = base + 2, i3 = base + 3;
        v0 = (i0 < N_NODES) ? g_deg[i0] : 0;
        v1 = (i1 < N_NODES) ? g_deg[i1] : 0;
        v2 = (i2 < N_NODES) ? g_deg[i2] : 0;
        v3 = (i3 < N_NODES) ? g_deg[i3] : 0;
    }
    int s = v0 + v1 + v2 + v3;
    int lane = t & 31, w = t >> 5;
    int incl = s;
#pragma unroll
    for (int off = 1; off < 32; off <<= 1) {
        int x = __shfl_up_sync(0xffffffffu, incl, off);
        if (lane >= off) incl += x;
    }
    __shared__ int wsum[8], wexcl[8];
    if (lane == 31) wsum[w] = incl;
    __syncthreads();
    if (t == 0) {
        int run = 0;
        for (int i = 0; i < 8; i++) { wexcl[i] = run; run += wsum[i]; }
    }
    __syncthreads();
    int excl_thread = wexcl[w] + (incl - s);
    int run = g_bscan[b] + excl_thread;
    if (base < N_NODES)     { g_rowptr[base] = run;     g_cursor[base] = run; }     run += v0;
    if (base + 1 < N_NODES) { g_rowptr[base + 1] = run; g_cursor[base + 1] = run; } run += v1;
    if (base + 2 < N_NODES) { g_rowptr[base + 2] = run; g_cursor[base + 2] = run; } run += v2;
    if (base + 3 < N_NODES) { g_rowptr[base + 3] = run; g_cursor[base + 3] = run; }
}

__global__ void k_scatter(const int* __restrict__ src, const int* __restrict__ dst,
                          const float* __restrict__ ew) {
    int i = blockIdx.x * blockDim.x + threadIdx.x;
    if (i < N_EDGES) {
        int d = dst[i];
        int p = atomicAdd(&g_cursor[d], 1);
        g_csrc[p] = src[i];
        g_cw[p]   = ew[i];
    }
}

// ---------------- dense GEMM: g_sup[M,64] = A[M,K] @ W[K,64] ----------------
// ASEL: 0 -> A = external pointer (x), 1 -> A = g_h (device-side symbol select)
// 256 threads, tile 256 rows x 64 cols, 8x8 per thread, no indexable locals.
#define FMA_ROW(CL, CH, AV)                                   \
    CL.x = fmaf(AV, b0.x, CL.x); CL.y = fmaf(AV, b0.y, CL.y); \
    CL.z = fmaf(AV, b0.z, CL.z); CL.w = fmaf(AV, b0.w, CL.w); \
    CH.x = fmaf(AV, b1.x, CH.x); CH.y = fmaf(AV, b1.y, CH.y); \
    CH.z = fmaf(AV, b1.z, CH.z); CH.w = fmaf(AV, b1.w, CH.w);

template <int K, int ASEL>
__global__ void __launch_bounds__(256) k_gemm64(const float* __restrict__ Aext,
                                                const float* __restrict__ W, int M) {
    const float* A = (ASEL == 1) ? (const float*)g_h : Aext;
    const int KC = 16;
    __shared__ float Xs[KC][260];  // [k][row], padded
    __shared__ float Ws[KC][64];   // [k][col]
    int t = threadIdx.x;
    int rbase = blockIdx.x * 256;
    int rg = t >> 3, cg = t & 7;

    float4 cL0 = {0,0,0,0}, cH0 = {0,0,0,0}, cL1 = {0,0,0,0}, cH1 = {0,0,0,0};
    float4 cL2 = {0,0,0,0}, cH2 = {0,0,0,0}, cL3 = {0,0,0,0}, cH3 = {0,0,0,0};
    float4 cL4 = {0,0,0,0}, cH4 = {0,0,0,0}, cL5 = {0,0,0,0}, cH5 = {0,0,0,0};
    float4 cL6 = {0,0,0,0}, cH6 = {0,0,0,0}, cL7 = {0,0,0,0}, cH7 = {0,0,0,0};

    for (int k0 = 0; k0 < K; k0 += KC) {
        // load A tile (256 x 16), transposed into Xs[k][row]
#pragma unroll
        for (int u = 0; u < 4; u++) {
            int id = t + 256 * u;          // 0..1023 float4s
            int row = id >> 2, j4 = id & 3;
            int grow = rbase + row;
            float4 v = make_float4(0.f, 0.f, 0.f, 0.f);
            if (grow < M) v = *(const float4*)(A + (size_t)grow * K + k0 + j4 * 4);
            Xs[j4 * 4 + 0][row] = v.x;
            Xs[j4 * 4 + 1][row] = v.y;
            Xs[j4 * 4 + 2][row] = v.z;
            Xs[j4 * 4 + 3][row] = v.w;
        }
        {   // load W chunk (16 x 64)
            int k = t >> 4, c4 = t & 15;
            float4 v = *(const float4*)(W + (size_t)(k0 + k) * 64 + c4 * 4);
            *(float4*)&Ws[k][c4 * 4] = v;
        }
        __syncthreads();
#pragma unroll
        for (int kk = 0; kk < KC; kk++) {
            float4 a0 = *(const float4*)&Xs[kk][rg * 8];
            float4 a1 = *(const float4*)&Xs[kk][rg * 8 + 4];
            float4 b0 = *(const float4*)&Ws[kk][cg * 8];
            float4 b1 = *(const float4*)&Ws[kk][cg * 8 + 4];
            FMA_ROW(cL0, cH0, a0.x)
            FMA_ROW(cL1, cH1, a0.y)
            FMA_ROW(cL2, cH2, a0.z)
            FMA_ROW(cL3, cH3, a0.w)
            FMA_ROW(cL4, cH4, a1.x)
            FMA_ROW(cL5, cH5, a1.y)
            FMA_ROW(cL6, cH6, a1.z)
            FMA_ROW(cL7, cH7, a1.w)
        }
        __syncthreads();
    }
    float* C = g_sup;
    int r0 = rbase + rg * 8;
#define STORE_ROW(I, CL, CH)                                            \
    if (r0 + I < M) {                                                   \
        *(float4*)(C + (size_t)(r0 + I) * 64 + cg * 8) = CL;            \
        *(float4*)(C + (size_t)(r0 + I) * 64 + cg * 8 + 4) = CH;        \
    }
    STORE_ROW(0, cL0, cH0)
    STORE_ROW(1, cL1, cH1)
    STORE_ROW(2, cL2, cH2)
    STORE_ROW(3, cL3, cH3)
    STORE_ROW(4, cL4, cH4)
    STORE_ROW(5, cL5, cH5)
    STORE_ROW(6, cL6, cH6)
    STORE_ROW(7, cL7, cH7)
#undef STORE_ROW
}

// ---------------- SpMM (D=64): g_h[n] = relu(sum_e w_e * g_sup[src_e] + bias) ----
// one warp per dst node; 8-deep edge unroll for MLP against L2 latency
__global__ void __launch_bounds__(256) k_spmm64(const float* __restrict__ bias) {
    int warp = threadIdx.x >> 5, lane = threadIdx.x & 31;
    int n = blockIdx.x * 8 + warp;
    if (n >= N_NODES) return;
    const float2* supv = (const float2*)g_sup;
    float2 acc = make_float2(0.f, 0.f);
    float2 acc2 = make_float2(0.f, 0.f);
    int e = g_rowptr[n];
    int end = e + g_deg[n];
    for (; e + 8 <= end; e += 8) {
        int s0 = __ldg(&g_csrc[e + 0]), s1 = __ldg(&g_csrc[e + 1]);
        int s2 = __ldg(&g_csrc[e + 2]), s3 = __ldg(&g_csrc[e + 3]);
        int s4 = __ldg(&g_csrc[e + 4]), s5 = __ldg(&g_csrc[e + 5]);
        int s6 = __ldg(&g_csrc[e + 6]), s7 = __ldg(&g_csrc[e + 7]);
        float w0 = __ldg(&g_cw[e + 0]), w1 = __ldg(&g_cw[e + 1]);
        float w2 = __ldg(&g_cw[e + 2]), w3 = __ldg(&g_cw[e + 3]);
        float w4 = __ldg(&g_cw[e + 4]), w5 = __ldg(&g_cw[e + 5]);
        float w6 = __ldg(&g_cw[e + 6]), w7 = __ldg(&g_cw[e + 7]);
        float2 v0 = supv[(size_t)s0 * 32 + lane];
        float2 v1 = supv[(size_t)s1 * 32 + lane];
        float2 v2 = supv[(size_t)s2 * 32 + lane];
        float2 v3 = supv[(size_t)s3 * 32 + lane];
        float2 v4 = supv[(size_t)s4 * 32 + lane];
        float2 v5 = supv[(size_t)s5 * 32 + lane];
        float2 v6 = supv[(size_t)s6 * 32 + lane];
        float2 v7 = supv[(size_t)s7 * 32 + lane];
        acc.x  = fmaf(w0, v0.x, acc.x);  acc.y  = fmaf(w0, v0.y, acc.y);
        acc2.x = fmaf(w1, v1.x, acc2.x); acc2.y = fmaf(w1, v1.y, acc2.y);
        acc.x  = fmaf(w2, v2.x, acc.x);  acc.y  = fmaf(w2, v2.y, acc.y);
        acc2.x = fmaf(w3, v3.x, acc2.x); acc2.y = fmaf(w3, v3.y, acc2.y);
        acc.x  = fmaf(w4, v4.x, acc.x);  acc.y  = fmaf(w4, v4.y, acc.y);
        acc2.x = fmaf(w5, v5.x, acc2.x); acc2.y = fmaf(w5, v5.y, acc2.y);
        acc.x  = fmaf(w6, v6.x, acc.x);  acc.y  = fmaf(w6, v6.y, acc.y);
        acc2.x = fmaf(w7, v7.x, acc2.x); acc2.y = fmaf(w7, v7.y, acc2.y);
    }
    for (; e < end; e++) {
        int s = __ldg(&g_csrc[e]);
        float w = __ldg(&g_cw[e]);
        float2 v = supv[(size_t)s * 32 + lane];
        acc.x = fmaf(w, v.x, acc.x); acc.y = fmaf(w, v.y, acc.y);
    }
    acc.x += acc2.x; acc.y += acc2.y;
    float2 bb = ((const float2*)bias)[lane];
    float ox = fmaxf(acc.x + bb.x, 0.f);
    float oy = fmaxf(acc.y + bb.y, 0.f);
    ((float2*)g_h)[(size_t)n * 32 + lane] = make_float2(ox, oy);
}

// ---------------- GEMM3: g_sup3[M,16] = g_h[M,64] @ W2[64,16] ----------------
__global__ void __launch_bounds__(256) k_gemm16(const float* __restrict__ W2, int M) {
    __shared__ float Ws[64 * 16];
    int t = threadIdx.x;
#pragma unroll
    for (int u = 0; u < 4; u++) Ws[t + 256 * u] = W2[t + 256 * u];
    __syncthreads();
    int idx = blockIdx.x * 256 + t;
    int n = idx >> 4, c = idx & 15;
    if (n >= M) return;
    const float4* arow = (const float4*)(g_h + (size_t)n * 64);
    float s = 0.f;
#pragma unroll
    for (int k4 = 0; k4 < 16; k4++) {
        float4 a = arow[k4];
        s = fmaf(a.x, Ws[(k4 * 4 + 0) * 16 + c], s);
        s = fmaf(a.y, Ws[(k4 * 4 + 1) * 16 + c], s);
        s = fmaf(a.z, Ws[(k4 * 4 + 2) * 16 + c], s);
        s = fmaf(a.w, Ws[(k4 * 4 + 3) * 16 + c], s);
    }
    g_sup3[(size_t)n * 16 + c] = s;
}

// ---------------- SpMM (D=16) + bias + log_softmax, fused ----------------
__global__ void __launch_bounds__(256) k_spmm16_lsm(const float* __restrict__ b2,
                                                    float* __restrict__ out) {
    int warp = threadIdx.x >> 5, lane = threadIdx.x & 31;
    int n = blockIdx.x * 16 + warp * 2 + (lane >> 4);  // N_NODES % 16 == 0
    int l = lane & 15;
    float acc = 0.f;
    int e = g_rowptr[n];
    int end = e + g_deg[n];
    for (; e + 4 <= end; e += 4) {
        int s0 = __ldg(&g_csrc[e + 0]), s1 = __ldg(&g_csrc[e + 1]);
        int s2 = __ldg(&g_csrc[e + 2]), s3 = __ldg(&g_csrc[e + 3]);
        float w0 = __ldg(&g_cw[e + 0]), w1 = __ldg(&g_cw[e + 1]);
        float w2 = __ldg(&g_cw[e + 2]), w3 = __ldg(&g_cw[e + 3]);
        acc = fmaf(w0, g_sup3[(size_t)s0 * 16 + l], acc);
        acc = fmaf(w1, g_sup3[(size_t)s1 * 16 + l], acc);
        acc = fmaf(w2, g_sup3[(size_t)s2 * 16 + l], acc);
        acc = fmaf(w3, g_sup3[(size_t)s3 * 16 + l], acc);
    }
    for (; e < end; e++) {
        acc = fmaf(__ldg(&g_cw[e]), g_sup3[(size_t)__ldg(&g_csrc[e]) * 16 + l], acc);
    }
    float y = acc + b2[l];
    float m = y;
#pragma unroll
    for (int off = 8; off; off >>= 1) m = fmaxf(m, __shfl_xor_sync(0xffffffffu, m, off));
    float ex = __expf(y - m);
    float ssum = ex;
#pragma unroll
    for (int off = 8; off; off >>= 1) ssum += __shfl_xor_sync(0xffffffffu, ssum, off);
    out[(size_t)n * 16 + l] = y - m - __logf(ssum);
}

// ---------------- launch ----------------
extern "C" void kernel_launch(void* const* d_in, const int* in_sizes, int n_in,
                              void* d_out, int out_size) {
    const float* x   = (const float*)d_in[0];
    const int*   src = (const int*)d_in[1];
    const int*   dst = (const int*)d_in[2];
    const float* ew  = (const float*)d_in[3];
    const float* W1  = (const float*)d_in[4];
    const float* b1  = (const float*)d_in[5];
    const float* Wh  = (const float*)d_in[6];
    const float* bh  = (const float*)d_in[7];
    const float* W2  = (const float*)d_in[8];
    const float* b2  = (const float*)d_in[9];
    float* out = (float*)d_out;

    // build dst-CSR
    k_zero_deg<<<(N_NODES + 255) / 256, 256>>>();
    k_hist<<<(N_EDGES + 255) / 256, 256>>>(dst);
    k_scan1<<<SCAN_BLOCKS, 256>>>();
    k_scan2<<<1, 128>>>(SCAN_BLOCKS);
    k_scan3<<<SCAN_BLOCKS, 256>>>();
    k_scatter<<<(N_EDGES + 255) / 256, 256>>>(src, dst, ew);

    // layer 1: x @ W1 -> g_sup ; spmm+b1, relu -> g_h
    k_gemm64<256, 0><<<(N_NODES + 255) / 256, 256>>>(x, W1, N_NODES);
    k_spmm64<<<(N_NODES + 7) / 8, 256>>>(b1);
    // layer 2: g_h @ Wh -> g_sup ; spmm+bh, relu -> g_h
    k_gemm64<64, 1><<<(N_NODES + 255) / 256, 256>>>(nullptr, Wh, N_NODES);
    k_spmm64<<<(N_NODES + 7) / 8, 256>>>(bh);
    // output layer: g_h @ W2 -> g_sup3 ; spmm+b2+log_softmax -> out
    k_gemm16<<<((N_NODES * 16) + 255) / 256, 256>>>(W2, N_NODES);
    k_spmm16_lsm<<<N_NODES / 16, 256>>>(b2, out);
}

// round 5
// speedup vs baseline: 1.1076x; 1.1076x over previous
#include <cuda_runtime.h>

#define N_NODES 100000
#define N_EDGES 1600000
#define SCAN_BLOCKS 98   // ceil(100000/1024)

// ---------------- scratch (device globals; no allocation allowed) ----------------
__device__ int   g_deg[N_NODES];
__device__ int   g_rowptr[N_NODES];
__device__ int   g_cursor[N_NODES];
__device__ int   g_bsum[128];
__device__ int   g_bscan[128];
__device__ int2  g_edge[N_EDGES];   // .x = src node, .y = float bits of edge weight
__device__ float g_sup[(size_t)N_NODES * 64];
__device__ float g_h[(size_t)N_NODES * 64];
__device__ float g_sup3[(size_t)N_NODES * 16];

// ---------------- CSR build ----------------
__global__ void k_zero_deg() {
    int i = blockIdx.x * blockDim.x + threadIdx.x;
    if (i < N_NODES) g_deg[i] = 0;
}

__global__ void k_hist(const int* __restrict__ dst) {
    int i = blockIdx.x * blockDim.x + threadIdx.x;
    if (i < N_EDGES) atomicAdd(&g_deg[dst[i]], 1);
}

// pass 1: per-1024-chunk sums
__global__ void k_scan1() {
    int b = blockIdx.x, t = threadIdx.x;
    int base = b * 1024 + t * 4;
    int s = 0;
#pragma unroll
    for (int j = 0; j < 4; j++) {
        int idx = base + j;
        if (idx < N_NODES) s += g_deg[idx];
    }
#pragma unroll
    for (int off = 16; off; off >>= 1) s += __shfl_down_sync(0xffffffffu, s, off);
    __shared__ int ws[8];
    if ((t & 31) == 0) ws[t >> 5] = s;
    __syncthreads();
    if (t == 0) {
        int tot = 0;
        for (int i = 0; i < 8; i++) tot += ws[i];
        g_bsum[b] = tot;
    }
}

// pass 2: exclusive scan of chunk sums (single block, 128 threads)
__global__ void k_scan2(int nblocks) {
    int t = threadIdx.x;
    int v = (t < nblocks) ? g_bsum[t] : 0;
    __shared__ int arr[128];
    arr[t] = v;
    __syncthreads();
    for (int off = 1; off < 128; off <<= 1) {
        int x = (t >= off) ? arr[t - off] : 0;
        __syncthreads();
        arr[t] += x;
        __syncthreads();
    }
    if (t < nblocks) g_bscan[t] = arr[t] - v;
}

// pass 3: per-chunk exclusive scan + chunk offset -> rowptr, cursor
__global__ void k_scan3() {
    int b = blockIdx.x, t = threadIdx.x;
    int base = b * 1024 + t * 4;
    int v0, v1, v2, v3;
    {
        int i0 = base, i1 = base + 1, i2 = base + 2, i3 = base + 3;
        v0 = (i0 < N_NODES) ? g_deg[i0] : 0;
        v1 = (i1 < N_NODES) ? g_deg[i1] : 0;
        v2 = (i2 < N_NODES) ? g_deg[i2] : 0;
        v3 = (i3 < N_NODES) ? g_deg[i3] : 0;
    }
    int s = v0 + v1 + v2 + v3;
    int lane = t & 31, w = t >> 5;
    int incl = s;
#pragma unroll
    for (int off = 1; off < 32; off <<= 1) {
        int x = __shfl_up_sync(0xffffffffu, incl, off);
        if (lane >= off) incl += x;
    }
    __shared__ int wsum[8], wexcl[8];
    if (lane == 31) wsum[w] = incl;
    __syncthreads();
    if (t == 0) {
        int run = 0;
        for (int i = 0; i < 8; i++) { wexcl[i] = run; run += wsum[i]; }
    }
    __syncthreads();
    int excl_thread = wexcl[w] + (incl - s);
    int run = g_bscan[b] + excl_thread;
    if (base < N_NODES)     { g_rowptr[base] = run;     g_cursor[base] = run; }     run += v0;
    if (base + 1 < N_NODES) { g_rowptr[base + 1] = run; g_cursor[base + 1] = run; } run += v1;
    if (base + 2 < N_NODES) { g_rowptr[base + 2] = run; g_cursor[base + 2] = run; } run += v2;
    if (base + 3 < N_NODES) { g_rowptr[base + 3] = run; g_cursor[base + 3] = run; }
}

__global__ void k_scatter(const int* __restrict__ src, const int* __restrict__ dst,
                          const float* __restrict__ ew) {
    int i = blockIdx.x * blockDim.x + threadIdx.x;
    if (i < N_EDGES) {
        int d = dst[i];
        int p = atomicAdd(&g_cursor[d], 1);
        g_edge[p] = make_int2(src[i], __float_as_int(ew[i]));
    }
}

// ---------------- dense GEMM: g_sup[M,64] = A[M,K] @ W[K,64] ----------------
// ASEL: 0 -> A = external pointer (x), 1 -> A = g_h (device-side symbol select)
#define FMA_ROW(CL, CH, AV)                                   \
    CL.x = fmaf(AV, b0.x, CL.x); CL.y = fmaf(AV, b0.y, CL.y); \
    CL.z = fmaf(AV, b0.z, CL.z); CL.w = fmaf(AV, b0.w, CL.w); \
    CH.x = fmaf(AV, b1.x, CH.x); CH.y = fmaf(AV, b1.y, CH.y); \
    CH.z = fmaf(AV, b1.z, CH.z); CH.w = fmaf(AV, b1.w, CH.w);

template <int K, int ASEL>
__global__ void __launch_bounds__(256) k_gemm64(const float* __restrict__ Aext,
                                                const float* __restrict__ W, int M) {
    const float* A = (ASEL == 1) ? (const float*)g_h : Aext;
    const int KC = 16;
    __shared__ float Xs[KC][260];  // [k][row], padded
    __shared__ float Ws[KC][64];   // [k][col]
    int t = threadIdx.x;
    int rbase = blockIdx.x * 256;
    int rg = t >> 3, cg = t & 7;

    float4 cL0 = {0,0,0,0}, cH0 = {0,0,0,0}, cL1 = {0,0,0,0}, cH1 = {0,0,0,0};
    float4 cL2 = {0,0,0,0}, cH2 = {0,0,0,0}, cL3 = {0,0,0,0}, cH3 = {0,0,0,0};
    float4 cL4 = {0,0,0,0}, cH4 = {0,0,0,0}, cL5 = {0,0,0,0}, cH5 = {0,0,0,0};
    float4 cL6 = {0,0,0,0}, cH6 = {0,0,0,0}, cL7 = {0,0,0,0}, cH7 = {0,0,0,0};

    for (int k0 = 0; k0 < K; k0 += KC) {
#pragma unroll
        for (int u = 0; u < 4; u++) {
            int id = t + 256 * u;          // 0..1023 float4s
            int row = id >> 2, j4 = id & 3;
            int grow = rbase + row;
            float4 v = make_float4(0.f, 0.f, 0.f, 0.f);
            if (grow < M) v = *(const float4*)(A + (size_t)grow * K + k0 + j4 * 4);
            Xs[j4 * 4 + 0][row] = v.x;
            Xs[j4 * 4 + 1][row] = v.y;
            Xs[j4 * 4 + 2][row] = v.z;
            Xs[j4 * 4 + 3][row] = v.w;
        }
        {   // load W chunk (16 x 64)
            int k = t >> 4, c4 = t & 15;
            float4 v = *(const float4*)(W + (size_t)(k0 + k) * 64 + c4 * 4);
            *(float4*)&Ws[k][c4 * 4] = v;
        }
        __syncthreads();
#pragma unroll
        for (int kk = 0; kk < KC; kk++) {
            float4 a0 = *(const float4*)&Xs[kk][rg * 8];
            float4 a1 = *(const float4*)&Xs[kk][rg * 8 + 4];
            float4 b0 = *(const float4*)&Ws[kk][cg * 8];
            float4 b1 = *(const float4*)&Ws[kk][cg * 8 + 4];
            FMA_ROW(cL0, cH0, a0.x)
            FMA_ROW(cL1, cH1, a0.y)
            FMA_ROW(cL2, cH2, a0.z)
            FMA_ROW(cL3, cH3, a0.w)
            FMA_ROW(cL4, cH4, a1.x)
            FMA_ROW(cL5, cH5, a1.y)
            FMA_ROW(cL6, cH6, a1.z)
            FMA_ROW(cL7, cH7, a1.w)
        }
        __syncthreads();
    }
    float* C = g_sup;
    int r0 = rbase + rg * 8;
#define STORE_ROW(I, CL, CH)                                            \
    if (r0 + I < M) {                                                   \
        *(float4*)(C + (size_t)(r0 + I) * 64 + cg * 8) = CL;            \
        *(float4*)(C + (size_t)(r0 + I) * 64 + cg * 8 + 4) = CH;        \
    }
    STORE_ROW(0, cL0, cH0)
    STORE_ROW(1, cL1, cH1)
    STORE_ROW(2, cL2, cH2)
    STORE_ROW(3, cL3, cH3)
    STORE_ROW(4, cL4, cH4)
    STORE_ROW(5, cL5, cH5)
    STORE_ROW(6, cL6, cH6)
    STORE_ROW(7, cL7, cH7)
#undef STORE_ROW
}

// ---------------- SpMM (D=64): g_h[n] = relu(sum_e w_e * g_sup[src_e] + bias) ----
__global__ void __launch_bounds__(256) k_spmm64(const float* __restrict__ bias) {
    int warp = threadIdx.x >> 5, lane = threadIdx.x & 31;
    int n = blockIdx.x * 8 + warp;
    if (n >= N_NODES) return;
    const float2* supv = (const float2*)g_sup;
    float2 acc = make_float2(0.f, 0.f);
    float2 acc2 = make_float2(0.f, 0.f);
    int e = g_rowptr[n];
    int end = e + g_deg[n];
    for (; e + 8 <= end; e += 8) {
        int2 e0 = __ldg(&g_edge[e + 0]), e1 = __ldg(&g_edge[e + 1]);
        int2 e2 = __ldg(&g_edge[e + 2]), e3 = __ldg(&g_edge[e + 3]);
        int2 e4 = __ldg(&g_edge[e + 4]), e5 = __ldg(&g_edge[e + 5]);
        int2 e6 = __ldg(&g_edge[e + 6]), e7 = __ldg(&g_edge[e + 7]);
        float2 v0 = supv[(size_t)e0.x * 32 + lane];
        float2 v1 = supv[(size_t)e1.x * 32 + lane];
        float2 v2 = supv[(size_t)e2.x * 32 + lane];
        float2 v3 = supv[(size_t)e3.x * 32 + lane];
        float2 v4 = supv[(size_t)e4.x * 32 + lane];
        float2 v5 = supv[(size_t)e5.x * 32 + lane];
        float2 v6 = supv[(size_t)e6.x * 32 + lane];
        float2 v7 = supv[(size_t)e7.x * 32 + lane];
        float w0 = __int_as_float(e0.y), w1 = __int_as_float(e1.y);
        float w2 = __int_as_float(e2.y), w3 = __int_as_float(e3.y);
        float w4 = __int_as_float(e4.y), w5 = __int_as_float(e5.y);
        float w6 = __int_as_float(e6.y), w7 = __int_as_float(e7.y);
        acc.x  = fmaf(w0, v0.x, acc.x);  acc.y  = fmaf(w0, v0.y, acc.y);
        acc2.x = fmaf(w1, v1.x, acc2.x); acc2.y = fmaf(w1, v1.y, acc2.y);
        acc.x  = fmaf(w2, v2.x, acc.x);  acc.y  = fmaf(w2, v2.y, acc.y);
        acc2.x = fmaf(w3, v3.x, acc2.x); acc2.y = fmaf(w3, v3.y, acc2.y);
        acc.x  = fmaf(w4, v4.x, acc.x);  acc.y  = fmaf(w4, v4.y, acc.y);
        acc2.x = fmaf(w5, v5.x, acc2.x); acc2.y = fmaf(w5, v5.y, acc2.y);
        acc.x  = fmaf(w6, v6.x, acc.x);  acc.y  = fmaf(w6, v6.y, acc.y);
        acc2.x = fmaf(w7, v7.x, acc2.x); acc2.y = fmaf(w7, v7.y, acc2.y);
    }
    for (; e < end; e++) {
        int2 ed = __ldg(&g_edge[e]);
        float w = __int_as_float(ed.y);
        float2 v = supv[(size_t)ed.x * 32 + lane];
        acc.x = fmaf(w, v.x, acc.x); acc.y = fmaf(w, v.y, acc.y);
    }
    acc.x += acc2.x; acc.y += acc2.y;
    float2 bb = ((const float2*)bias)[lane];
    float ox = fmaxf(acc.x + bb.x, 0.f);
    float oy = fmaxf(acc.y + bb.y, 0.f);
    ((float2*)g_h)[(size_t)n * 32 + lane] = make_float2(ox, oy);
}

// ---------------- GEMM3: g_sup3[M,16] = g_h[M,64] @ W2[64,16] ----------------
__global__ void __launch_bounds__(256) k_gemm16(const float* __restrict__ W2, int M) {
    __shared__ float Ws[64 * 16];
    int t = threadIdx.x;
#pragma unroll
    for (int u = 0; u < 4; u++) Ws[t + 256 * u] = W2[t + 256 * u];
    __syncthreads();
    int idx = blockIdx.x * 256 + t;
    int n = idx >> 4, c = idx & 15;
    if (n >= M) return;
    const float4* arow = (const float4*)(g_h + (size_t)n * 64);
    float s = 0.f;
#pragma unroll
    for (int k4 = 0; k4 < 16; k4++) {
        float4 a = arow[k4];
        s = fmaf(a.x, Ws[(k4 * 4 + 0) * 16 + c], s);
        s = fmaf(a.y, Ws[(k4 * 4 + 1) * 16 + c], s);
        s = fmaf(a.z, Ws[(k4 * 4 + 2) * 16 + c], s);
        s = fmaf(a.w, Ws[(k4 * 4 + 3) * 16 + c], s);
    }
    g_sup3[(size_t)n * 16 + c] = s;
}

// ---------------- SpMM (D=16) + bias + log_softmax, fused ----------------
__global__ void __launch_bounds__(256) k_spmm16_lsm(const float* __restrict__ b2,
                                                    float* __restrict__ out) {
    int warp = threadIdx.x >> 5, lane = threadIdx.x & 31;
    int n = blockIdx.x * 16 + warp * 2 + (lane >> 4);  // N_NODES % 16 == 0
    int l = lane & 15;
    float acc = 0.f;
    int e = g_rowptr[n];
    int end = e + g_deg[n];
    for (; e + 4 <= end; e += 4) {
        int2 e0 = __ldg(&g_edge[e + 0]), e1 = __ldg(&g_edge[e + 1]);
        int2 e2 = __ldg(&g_edge[e + 2]), e3 = __ldg(&g_edge[e + 3]);
        acc = fmaf(__int_as_float(e0.y), g_sup3[(size_t)e0.x * 16 + l], acc);
        acc = fmaf(__int_as_float(e1.y), g_sup3[(size_t)e1.x * 16 + l], acc);
        acc = fmaf(__int_as_float(e2.y), g_sup3[(size_t)e2.x * 16 + l], acc);
        acc = fmaf(__int_as_float(e3.y), g_sup3[(size_t)e3.x * 16 + l], acc);
    }
    for (; e < end; e++) {
        int2 ed = __ldg(&g_edge[e]);
        acc = fmaf(__int_as_float(ed.y), g_sup3[(size_t)ed.x * 16 + l], acc);
    }
    float y = acc + b2[l];
    float m = y;
#pragma unroll
    for (int off = 8; off; off >>= 1) m = fmaxf(m, __shfl_xor_sync(0xffffffffu, m, off));
    float ex = __expf(y - m);
    float ssum = ex;
#pragma unroll
    for (int off = 8; off; off >>= 1) ssum += __shfl_xor_sync(0xffffffffu, ssum, off);
    out[(size_t)n * 16 + l] = y - m - __logf(ssum);
}

// ---------------- launch ----------------
extern "C" void kernel_launch(void* const* d_in, const int* in_sizes, int n_in,
                              void* d_out, int out_size) {
    const float* x   = (const float*)d_in[0];
    const int*   src = (const int*)d_in[1];
    const int*   dst = (const int*)d_in[2];
    const float* ew  = (const float*)d_in[3];
    const float* W1  = (const float*)d_in[4];
    const float* b1  = (const float*)d_in[5];
    const float* Wh  = (const float*)d_in[6];
    const float* bh  = (const float*)d_in[7];
    const float* W2  = (const float*)d_in[8];
    const float* b2  = (const float*)d_in[9];
    float* out = (float*)d_out;

    // Fork: CSR build on side stream, GEMM1 on main stream (independent work).
    cudaStream_t s2;
    cudaStreamCreateWithFlags(&s2, cudaStreamNonBlocking);
    cudaEvent_t evFork, evJoin;
    cudaEventCreateWithFlags(&evFork, cudaEventDisableTiming);
    cudaEventCreateWithFlags(&evJoin, cudaEventDisableTiming);

    cudaEventRecord(evFork, 0);
    cudaStreamWaitEvent(s2, evFork, 0);

    // CSR chain (side stream)
    k_zero_deg<<<(N_NODES + 255) / 256, 256, 0, s2>>>();
    k_hist<<<(N_EDGES + 255) / 256, 256, 0, s2>>>(dst);
    k_scan1<<<SCAN_BLOCKS, 256, 0, s2>>>();
    k_scan2<<<1, 128, 0, s2>>>(SCAN_BLOCKS);
    k_scan3<<<SCAN_BLOCKS, 256, 0, s2>>>();
    k_scatter<<<(N_EDGES + 255) / 256, 256, 0, s2>>>(src, dst, ew);
    cudaEventRecord(evJoin, s2);

    // GEMM1 concurrently on main stream
    k_gemm64<256, 0><<<(N_NODES + 255) / 256, 256>>>(x, W1, N_NODES);

    // Join, then the dependent chain
    cudaStreamWaitEvent(0, evJoin, 0);
    k_spmm64<<<(N_NODES + 7) / 8, 256>>>(b1);
    k_gemm64<64, 1><<<(N_NODES + 255) / 256, 256>>>(nullptr, Wh, N_NODES);
    k_spmm64<<<(N_NODES + 7) / 8, 256>>>(bh);
    k_gemm16<<<((N_NODES * 16) + 255) / 256, 256>>>(W2, N_NODES);
    k_spmm16_lsm<<<N_NODES / 16, 256>>>(b2, out);
}

// round 6
// speedup vs baseline: 1.1889x; 1.0734x over previous
#include <cuda_runtime.h>
#include <cuda_fp16.h>

#define N_NODES 100000
#define N_EDGES 1600000
#define SCAN_BLOCKS 98   // ceil(100000/1024)

// ---------------- scratch (device globals; no allocation allowed) ----------------
__device__ int    g_deg[N_NODES];
__device__ int    g_rowptr[N_NODES];
__device__ int    g_cursor[N_NODES];
__device__ int    g_bsum[128];
__device__ int    g_bscan[128];
__device__ int2   g_edge[N_EDGES];   // .x = src node, .y = float bits of edge weight
__device__ __half g_suph[(size_t)N_NODES * 64];  // support matrix in fp16
__device__ float  g_h[(size_t)N_NODES * 64];
__device__ float  g_sup3[(size_t)N_NODES * 16];

// ---------------- CSR build ----------------
__global__ void k_zero_deg() {
    int i = blockIdx.x * blockDim.x + threadIdx.x;
    if (i < N_NODES) g_deg[i] = 0;
}

__global__ void k_hist(const int* __restrict__ dst) {
    int i = blockIdx.x * blockDim.x + threadIdx.x;
    if (i < N_EDGES) atomicAdd(&g_deg[dst[i]], 1);
}

__global__ void k_scan1() {
    int b = blockIdx.x, t = threadIdx.x;
    int base = b * 1024 + t * 4;
    int s = 0;
#pragma unroll
    for (int j = 0; j < 4; j++) {
        int idx = base + j;
        if (idx < N_NODES) s += g_deg[idx];
    }
#pragma unroll
    for (int off = 16; off; off >>= 1) s += __shfl_down_sync(0xffffffffu, s, off);
    __shared__ int ws[8];
    if ((t & 31) == 0) ws[t >> 5] = s;
    __syncthreads();
    if (t == 0) {
        int tot = 0;
        for (int i = 0; i < 8; i++) tot += ws[i];
        g_bsum[b] = tot;
    }
}

__global__ void k_scan2(int nblocks) {
    int t = threadIdx.x;
    int v = (t < nblocks) ? g_bsum[t] : 0;
    __shared__ int arr[128];
    arr[t] = v;
    __syncthreads();
    for (int off = 1; off < 128; off <<= 1) {
        int x = (t >= off) ? arr[t - off] : 0;
        __syncthreads();
        arr[t] += x;
        __syncthreads();
    }
    if (t < nblocks) g_bscan[t] = arr[t] - v;
}

__global__ void k_scan3() {
    int b = blockIdx.x, t = threadIdx.x;
    int base = b * 1024 + t * 4;
    int v0, v1, v2, v3;
    {
        int i0 = base, i1 = base + 1, i2 = base + 2, i3 = base + 3;
        v0 = (i0 < N_NODES) ? g_deg[i0] : 0;
        v1 = (i1 < N_NODES) ? g_deg[i1] : 0;
        v2 = (i2 < N_NODES) ? g_deg[i2] : 0;
        v3 = (i3 < N_NODES) ? g_deg[i3] : 0;
    }
    int s = v0 + v1 + v2 + v3;
    int lane = t & 31, w = t >> 5;
    int incl = s;
#pragma unroll
    for (int off = 1; off < 32; off <<= 1) {
        int x = __shfl_up_sync(0xffffffffu, incl, off);
        if (lane >= off) incl += x;
    }
    __shared__ int wsum[8], wexcl[8];
    if (lane == 31) wsum[w] = incl;
    __syncthreads();
    if (t == 0) {
        int run = 0;
        for (int i = 0; i < 8; i++) { wexcl[i] = run; run += wsum[i]; }
    }
    __syncthreads();
    int excl_thread = wexcl[w] + (incl - s);
    int run = g_bscan[b] + excl_thread;
    if (base < N_NODES)     { g_rowptr[base] = run;     g_cursor[base] = run; }     run += v0;
    if (base + 1 < N_NODES) { g_rowptr[base + 1] = run; g_cursor[base + 1] = run; } run += v1;
    if (base + 2 < N_NODES) { g_rowptr[base + 2] = run; g_cursor[base + 2] = run; } run += v2;
    if (base + 3 < N_NODES) { g_rowptr[base + 3] = run; g_cursor[base + 3] = run; }
}

__global__ void k_scatter(const int* __restrict__ src, const int* __restrict__ dst,
                          const float* __restrict__ ew) {
    int i = blockIdx.x * blockDim.x + threadIdx.x;
    if (i < N_EDGES) {
        int d = dst[i];
        int p = atomicAdd(&g_cursor[d], 1);
        g_edge[p] = make_int2(src[i], __float_as_int(ew[i]));
    }
}

// ---------------- dense GEMM: g_suph[M,64] = half(A[M,K] @ W[K,64]) ----------------
// ASEL: 0 -> A = external pointer (x), 1 -> A = g_h
#define FMA_ROW(CL, CH, AV)                                   \
    CL.x = fmaf(AV, b0.x, CL.x); CL.y = fmaf(AV, b0.y, CL.y); \
    CL.z = fmaf(AV, b0.z, CL.z); CL.w = fmaf(AV, b0.w, CL.w); \
    CH.x = fmaf(AV, b1.x, CH.x); CH.y = fmaf(AV, b1.y, CH.y); \
    CH.z = fmaf(AV, b1.z, CH.z); CH.w = fmaf(AV, b1.w, CH.w);

__device__ __forceinline__ void store_row_half(__half* p, float4 a, float4 b) {
    __half2 h0 = __floats2half2_rn(a.x, a.y);
    __half2 h1 = __floats2half2_rn(a.z, a.w);
    __half2 h2 = __floats2half2_rn(b.x, b.y);
    __half2 h3 = __floats2half2_rn(b.z, b.w);
    uint4 u;
    u.x = *(unsigned int*)&h0;
    u.y = *(unsigned int*)&h1;
    u.z = *(unsigned int*)&h2;
    u.w = *(unsigned int*)&h3;
    *(uint4*)p = u;
}

template <int K, int ASEL>
__global__ void __launch_bounds__(256) k_gemm64(const float* __restrict__ Aext,
                                                const float* __restrict__ W, int M) {
    const float* A = (ASEL == 1) ? (const float*)g_h : Aext;
    const int KC = 16;
    __shared__ float Xs[KC][260];
    __shared__ float Ws[KC][64];
    int t = threadIdx.x;
    int rbase = blockIdx.x * 256;
    int rg = t >> 3, cg = t & 7;

    float4 cL0 = {0,0,0,0}, cH0 = {0,0,0,0}, cL1 = {0,0,0,0}, cH1 = {0,0,0,0};
    float4 cL2 = {0,0,0,0}, cH2 = {0,0,0,0}, cL3 = {0,0,0,0}, cH3 = {0,0,0,0};
    float4 cL4 = {0,0,0,0}, cH4 = {0,0,0,0}, cL5 = {0,0,0,0}, cH5 = {0,0,0,0};
    float4 cL6 = {0,0,0,0}, cH6 = {0,0,0,0}, cL7 = {0,0,0,0}, cH7 = {0,0,0,0};

    for (int k0 = 0; k0 < K; k0 += KC) {
#pragma unroll
        for (int u = 0; u < 4; u++) {
            int id = t + 256 * u;
            int row = id >> 2, j4 = id & 3;
            int grow = rbase + row;
            float4 v = make_float4(0.f, 0.f, 0.f, 0.f);
            if (grow < M) v = *(const float4*)(A + (size_t)grow * K + k0 + j4 * 4);
            Xs[j4 * 4 + 0][row] = v.x;
            Xs[j4 * 4 + 1][row] = v.y;
            Xs[j4 * 4 + 2][row] = v.z;
            Xs[j4 * 4 + 3][row] = v.w;
        }
        {
            int k = t >> 4, c4 = t & 15;
            float4 v = *(const float4*)(W + (size_t)(k0 + k) * 64 + c4 * 4);
            *(float4*)&Ws[k][c4 * 4] = v;
        }
        __syncthreads();
#pragma unroll
        for (int kk = 0; kk < KC; kk++) {
            float4 a0 = *(const float4*)&Xs[kk][rg * 8];
            float4 a1 = *(const float4*)&Xs[kk][rg * 8 + 4];
            float4 b0 = *(const float4*)&Ws[kk][cg * 8];
            float4 b1 = *(const float4*)&Ws[kk][cg * 8 + 4];
            FMA_ROW(cL0, cH0, a0.x)
            FMA_ROW(cL1, cH1, a0.y)
            FMA_ROW(cL2, cH2, a0.z)
            FMA_ROW(cL3, cH3, a0.w)
            FMA_ROW(cL4, cH4, a1.x)
            FMA_ROW(cL5, cH5, a1.y)
            FMA_ROW(cL6, cH6, a1.z)
            FMA_ROW(cL7, cH7, a1.w)
        }
        __syncthreads();
    }
    int r0 = rbase + rg * 8;
#define STORE_ROW(I, CL, CH)                                                        \
    if (r0 + I < M) store_row_half(g_suph + (size_t)(r0 + I) * 64 + cg * 8, CL, CH);
    STORE_ROW(0, cL0, cH0)
    STORE_ROW(1, cL1, cH1)
    STORE_ROW(2, cL2, cH2)
    STORE_ROW(3, cL3, cH3)
    STORE_ROW(4, cL4, cH4)
    STORE_ROW(5, cL5, cH5)
    STORE_ROW(6, cL6, cH6)
    STORE_ROW(7, cL7, cH7)
#undef STORE_ROW
}

// ---------------- SpMM (D=64) over fp16 support ----------------
// PROJ=0: h[n] = relu(agg + bias) -> g_h (fp32)
// PROJ=1: h[n] = relu(agg + bias), then g_sup3[n] = h[n] @ W2  (fused GEMM3)
// grid = N_NODES/8 exactly (100000 % 8 == 0): no early exit, block-uniform.
template <int PROJ>
__global__ void __launch_bounds__(256) k_spmm64(const float* __restrict__ bias,
                                                const float* __restrict__ W2) {
    __shared__ float W2s[PROJ ? 64 * 16 : 1];
    __shared__ float hb[PROJ ? 8 : 1][PROJ ? 64 : 1];
    int t = threadIdx.x;
    if (PROJ) {
#pragma unroll
        for (int u = 0; u < 4; u++) W2s[t + 256 * u] = W2[t + 256 * u];
        __syncthreads();
    }
    int warp = t >> 5, lane = t & 31;
    int n = blockIdx.x * 8 + warp;
    const __half2* supv = (const __half2*)g_suph;
    float2 acc = make_float2(0.f, 0.f);
    float2 acc2 = make_float2(0.f, 0.f);
    int e = g_rowptr[n];
    int end = e + g_deg[n];
    for (; e + 8 <= end; e += 8) {
        int2 e0 = __ldg(&g_edge[e + 0]), e1 = __ldg(&g_edge[e + 1]);
        int2 e2 = __ldg(&g_edge[e + 2]), e3 = __ldg(&g_edge[e + 3]);
        int2 e4 = __ldg(&g_edge[e + 4]), e5 = __ldg(&g_edge[e + 5]);
        int2 e6 = __ldg(&g_edge[e + 6]), e7 = __ldg(&g_edge[e + 7]);
        float2 v0 = __half22float2(supv[(size_t)e0.x * 32 + lane]);
        float2 v1 = __half22float2(supv[(size_t)e1.x * 32 + lane]);
        float2 v2 = __half22float2(supv[(size_t)e2.x * 32 + lane]);
        float2 v3 = __half22float2(supv[(size_t)e3.x * 32 + lane]);
        float2 v4 = __half22float2(supv[(size_t)e4.x * 32 + lane]);
        float2 v5 = __half22float2(supv[(size_t)e5.x * 32 + lane]);
        float2 v6 = __half22float2(supv[(size_t)e6.x * 32 + lane]);
        float2 v7 = __half22float2(supv[(size_t)e7.x * 32 + lane]);
        float w0 = __int_as_float(e0.y), w1 = __int_as_float(e1.y);
        float w2 = __int_as_float(e2.y), w3 = __int_as_float(e3.y);
        float w4 = __int_as_float(e4.y), w5 = __int_as_float(e5.y);
        float w6 = __int_as_float(e6.y), w7 = __int_as_float(e7.y);
        acc.x  = fmaf(w0, v0.x, acc.x);  acc.y  = fmaf(w0, v0.y, acc.y);
        acc2.x = fmaf(w1, v1.x, acc2.x); acc2.y = fmaf(w1, v1.y, acc2.y);
        acc.x  = fmaf(w2, v2.x, acc.x);  acc.y  = fmaf(w2, v2.y, acc.y);
        acc2.x = fmaf(w3, v3.x, acc2.x); acc2.y = fmaf(w3, v3.y, acc2.y);
        acc.x  = fmaf(w4, v4.x, acc.x);  acc.y  = fmaf(w4, v4.y, acc.y);
        acc2.x = fmaf(w5, v5.x, acc2.x); acc2.y = fmaf(w5, v5.y, acc2.y);
        acc.x  = fmaf(w6, v6.x, acc.x);  acc.y  = fmaf(w6, v6.y, acc.y);
        acc2.x = fmaf(w7, v7.x, acc2.x); acc2.y = fmaf(w7, v7.y, acc2.y);
    }
    for (; e < end; e++) {
        int2 ed = __ldg(&g_edge[e]);
        float w = __int_as_float(ed.y);
        float2 v = __half22float2(supv[(size_t)ed.x * 32 + lane]);
        acc.x = fmaf(w, v.x, acc.x); acc.y = fmaf(w, v.y, acc.y);
    }
    acc.x += acc2.x; acc.y += acc2.y;
    float2 bb = ((const float2*)bias)[lane];
    float ox = fmaxf(acc.x + bb.x, 0.f);
    float oy = fmaxf(acc.y + bb.y, 0.f);
    if (PROJ) {
        hb[warp][2 * lane] = ox;
        hb[warp][2 * lane + 1] = oy;
        __syncwarp();
        if (lane < 16) {
            float s = 0.f;
#pragma unroll
            for (int k = 0; k < 64; k += 4) {
                s = fmaf(hb[warp][k + 0], W2s[(k + 0) * 16 + lane], s);
                s = fmaf(hb[warp][k + 1], W2s[(k + 1) * 16 + lane], s);
                s = fmaf(hb[warp][k + 2], W2s[(k + 2) * 16 + lane], s);
                s = fmaf(hb[warp][k + 3], W2s[(k + 3) * 16 + lane], s);
            }
            g_sup3[(size_t)n * 16 + lane] = s;
        }
    } else {
        ((float2*)g_h)[(size_t)n * 32 + lane] = make_float2(ox, oy);
    }
}

// ---------------- SpMM (D=16) + bias + log_softmax, fused ----------------
__global__ void __launch_bounds__(256) k_spmm16_lsm(const float* __restrict__ b2,
                                                    float* __restrict__ out) {
    int warp = threadIdx.x >> 5, lane = threadIdx.x & 31;
    int n = blockIdx.x * 16 + warp * 2 + (lane >> 4);  // N_NODES % 16 == 0
    int l = lane & 15;
    float acc = 0.f;
    int e = g_rowptr[n];
    int end = e + g_deg[n];
    for (; e + 4 <= end; e += 4) {
        int2 e0 = __ldg(&g_edge[e + 0]), e1 = __ldg(&g_edge[e + 1]);
        int2 e2 = __ldg(&g_edge[e + 2]), e3 = __ldg(&g_edge[e + 3]);
        acc = fmaf(__int_as_float(e0.y), g_sup3[(size_t)e0.x * 16 + l], acc);
        acc = fmaf(__int_as_float(e1.y), g_sup3[(size_t)e1.x * 16 + l], acc);
        acc = fmaf(__int_as_float(e2.y), g_sup3[(size_t)e2.x * 16 + l], acc);
        acc = fmaf(__int_as_float(e3.y), g_sup3[(size_t)e3.x * 16 + l], acc);
    }
    for (; e < end; e++) {
        int2 ed = __ldg(&g_edge[e]);
        acc = fmaf(__int_as_float(ed.y), g_sup3[(size_t)ed.x * 16 + l], acc);
    }
    float y = acc + b2[l];
    float m = y;
#pragma unroll
    for (int off = 8; off; off >>= 1) m = fmaxf(m, __shfl_xor_sync(0xffffffffu, m, off));
    float ex = __expf(y - m);
    float ssum = ex;
#pragma unroll
    for (int off = 8; off; off >>= 1) ssum += __shfl_xor_sync(0xffffffffu, ssum, off);
    out[(size_t)n * 16 + l] = y - m - __logf(ssum);
}

// ---------------- launch ----------------
extern "C" void kernel_launch(void* const* d_in, const int* in_sizes, int n_in,
                              void* d_out, int out_size) {
    const float* x   = (const float*)d_in[0];
    const int*   src = (const int*)d_in[1];
    const int*   dst = (const int*)d_in[2];
    const float* ew  = (const float*)d_in[3];
    const float* W1  = (const float*)d_in[4];
    const float* b1  = (const float*)d_in[5];
    const float* Wh  = (const float*)d_in[6];
    const float* bh  = (const float*)d_in[7];
    const float* W2  = (const float*)d_in[8];
    const float* b2  = (const float*)d_in[9];
    float* out = (float*)d_out;

    // Fork: CSR build on side stream, GEMM1 on main stream (independent work).
    cudaStream_t s2;
    cudaStreamCreateWithFlags(&s2, cudaStreamNonBlocking);
    cudaEvent_t evFork, evJoin;
    cudaEventCreateWithFlags(&evFork, cudaEventDisableTiming);
    cudaEventCreateWithFlags(&evJoin, cudaEventDisableTiming);

    cudaEventRecord(evFork, 0);
    cudaStreamWaitEvent(s2, evFork, 0);

    // CSR chain (side stream)
    k_zero_deg<<<(N_NODES + 255) / 256, 256, 0, s2>>>();
    k_hist<<<(N_EDGES + 255) / 256, 256, 0, s2>>>(dst);
    k_scan1<<<SCAN_BLOCKS, 256, 0, s2>>>();
    k_scan2<<<1, 128, 0, s2>>>(SCAN_BLOCKS);
    k_scan3<<<SCAN_BLOCKS, 256, 0, s2>>>();
    k_scatter<<<(N_EDGES + 255) / 256, 256, 0, s2>>>(src, dst, ew);
    cudaEventRecord(evJoin, s2);

    // GEMM1 concurrently on main stream
    k_gemm64<256, 0><<<(N_NODES + 255) / 256, 256>>>(x, W1, N_NODES);

    // Join, then the dependent chain
    cudaStreamWaitEvent(0, evJoin, 0);
    k_spmm64<0><<<N_NODES / 8, 256>>>(b1, nullptr);              // -> g_h
    k_gemm64<64, 1><<<(N_NODES + 255) / 256, 256>>>(nullptr, Wh, N_NODES);  // -> g_suph
    k_spmm64<1><<<N_NODES / 8, 256>>>(bh, W2);                   // -> g_sup3 (fused GEMM3)
    k_spmm16_lsm<<<N_NODES / 16, 256>>>(b2, out);
}